// round 3
// baseline (speedup 1.0000x reference)
#include <cuda_runtime.h>
#include <cuda_bf16.h>

#define RDIM 256
#define SDIM 256

__global__ __launch_bounds__(256)
void ipm_kernel(const float* __restrict__ msm,
                const int* __restrict__ refm,     // bool promoted to int32
                const int* __restrict__ srcm,     // bool promoted to int32
                float* __restrict__ out_score,
                float* __restrict__ out_corr)     // bool output stored as float32
{
    const int p = blockIdx.x;
    const int t = threadIdx.x;   // 0..255: owns column t AND row t of this p-slice

    const float* __restrict__ tile = msm + (size_t)p * RDIM * SDIM;
    float* __restrict__ oscore = out_score + (size_t)p * RDIM * SDIM;
    float* __restrict__ ocorr  = out_corr  + (size_t)p * RDIM * SDIM;

    // ---------------- column top-3 (scan r, coalesced across lanes) ----------
    float cv0 = -1e30f, cv1 = -1e30f, cv2 = -1e30f;
    int   ci0 = 0,      ci1 = 0,      ci2 = 0;
    {
        #pragma unroll 4
        for (int r = 0; r < RDIM; ++r) {
            float v = __expf(tile[r * SDIM + t]);
            if (v > cv0)      { cv2 = cv1; ci2 = ci1; cv1 = cv0; ci1 = ci0; cv0 = v; ci0 = r; }
            else if (v > cv1) { cv2 = cv1; ci2 = ci1; cv1 = v;   ci1 = r; }
            else if (v > cv2) { cv2 = v;   ci2 = r; }
        }
    }

    // ---------------- row top-3 (contiguous float4 per thread) ---------------
    float rv0 = -1e30f, rv1 = -1e30f, rv2 = -1e30f;
    int   ri0 = 0,      ri1 = 0,      ri2 = 0;
    {
        const float4* __restrict__ row = (const float4*)(tile + (size_t)t * SDIM);
        #pragma unroll 4
        for (int j = 0; j < SDIM / 4; ++j) {
            float4 q = row[j];
            float vals[4] = {q.x, q.y, q.z, q.w};
            #pragma unroll
            for (int u = 0; u < 4; ++u) {
                float v = __expf(vals[u]);
                int s = j * 4 + u;
                if (v > rv0)      { rv2 = rv1; ri2 = ri1; rv1 = rv0; ri1 = ri0; rv0 = v; ri0 = s; }
                else if (v > rv1) { rv2 = rv1; ri2 = ri1; rv1 = v;   ri1 = s; }
                else if (v > rv2) { rv2 = v;   ri2 = s; }
            }
        }
    }

    // ---------------- zero-fill both output tiles (float4 streaming) ---------
    {
        float4 z4 = make_float4(0.f, 0.f, 0.f, 0.f);
        float4* zs = (float4*)oscore;
        float4* zc = (float4*)ocorr;
        #pragma unroll 4
        for (int i = t; i < (RDIM * SDIM) / 4; i += 256) {
            zs[i] = z4;
            zc[i] = z4;
        }
    }
    __syncthreads();   // zero-fill by whole block visible before scatter

    // ---------------- scatter ------------------------------------------------
    // Row t's top-3 along S
    {
        const bool mr = refm[(size_t)p * RDIM + t] != 0;
        float vs[3] = {rv0, rv1, rv2};
        int   is[3] = {ri0, ri1, ri2};
        #pragma unroll
        for (int k = 0; k < 3; ++k) {
            int s = is[k];
            float v = vs[k];
            atomicAdd(&oscore[t * SDIM + s], 0.5f * v);
            if (v > 0.0f && mr && srcm[(size_t)p * SDIM + s] != 0)
                ocorr[t * SDIM + s] = 1.0f;   // idempotent write, benign race
        }
    }
    // Column t's top-3 along R
    {
        const bool ms = srcm[(size_t)p * SDIM + t] != 0;
        float vs[3] = {cv0, cv1, cv2};
        int   is[3] = {ci0, ci1, ci2};
        #pragma unroll
        for (int k = 0; k < 3; ++k) {
            int r = is[k];
            float v = vs[k];
            atomicAdd(&oscore[r * SDIM + t], 0.5f * v);
            if (v > 0.0f && ms && refm[(size_t)p * RDIM + r] != 0)
                ocorr[r * SDIM + t] = 1.0f;
        }
    }
}

extern "C" void kernel_launch(void* const* d_in, const int* in_sizes, int n_in,
                              void* d_out, int out_size)
{
    // metadata order: matching_score_map [P,R,S] f32, node_corr_scores [P] f32 (unused),
    //                 ref_knn_masks [P,R] bool->int32, src_knn_masks [P,S] bool->int32
    const float* msm  = (const float*)d_in[0];
    const int*   refm = (const int*)d_in[2];
    const int*   srcm = (const int*)d_in[3];

    const int P = in_sizes[1];                 // node_corr_scores has P elements
    float* out_score = (float*)d_out;
    float* out_corr  = out_score + (size_t)P * RDIM * SDIM;  // bool output as float32

    ipm_kernel<<<P, 256>>>(msm, refm, srcm, out_score, out_corr);
}

// round 4
// speedup vs baseline: 1.3864x; 1.3864x over previous
#include <cuda_runtime.h>
#include <cuda_bf16.h>

#define RDIM 256
#define SDIM 256

__global__ __launch_bounds__(512)
void ipm_kernel(const float* __restrict__ msm,
                const int* __restrict__ refm,     // bool promoted to int32
                const int* __restrict__ srcm,     // bool promoted to int32
                float* __restrict__ out_score,
                float* __restrict__ out_corr)     // bool output stored as float32
{
    const int p = blockIdx.x;
    const int tid = threadIdx.x;                  // 0..511

    const float* __restrict__ tile = msm + (size_t)p * RDIM * SDIM;
    float* __restrict__ oscore = out_score + (size_t)p * RDIM * SDIM;
    float* __restrict__ ocorr  = out_corr  + (size_t)p * RDIM * SDIM;

    float v0 = -1e30f, v1 = -1e30f, v2 = -1e30f;  // top-3 values
    int   i0 = 0,      i1 = 0,      i2 = 0;       // top-3 indices

    if (tid < 256) {
        // ---- column top-3 for column t = tid (scan r; coalesced across lanes)
        const int t = tid;
        #pragma unroll 8
        for (int r = 0; r < RDIM; ++r) {
            float v = __expf(tile[r * SDIM + t]);
            if (v > v0)      { v2 = v1; i2 = i1; v1 = v0; i1 = i0; v0 = v; i0 = r; }
            else if (v > v1) { v2 = v1; i2 = i1; v1 = v;  i1 = r; }
            else if (v > v2) { v2 = v;  i2 = r; }
        }
    } else {
        // ---- row top-3 for row t = tid-256 (contiguous float4 per thread)
        const int t = tid - 256;
        const float4* __restrict__ row = (const float4*)(tile + (size_t)t * SDIM);
        #pragma unroll 8
        for (int j = 0; j < SDIM / 4; ++j) {
            float4 q = row[j];
            float vals[4] = {q.x, q.y, q.z, q.w};
            #pragma unroll
            for (int u = 0; u < 4; ++u) {
                float v = __expf(vals[u]);
                int s = j * 4 + u;
                if (v > v0)      { v2 = v1; i2 = i1; v1 = v0; i1 = i0; v0 = v; i0 = s; }
                else if (v > v1) { v2 = v1; i2 = i1; v1 = v;  i1 = s; }
                else if (v > v2) { v2 = v;  i2 = s; }
            }
        }
    }

    // ---------------- zero-fill both output tiles (512 threads, float4) ------
    {
        float4 z4 = make_float4(0.f, 0.f, 0.f, 0.f);
        float4* zs = (float4*)oscore;
        float4* zc = (float4*)ocorr;
        #pragma unroll 8
        for (int i = tid; i < (RDIM * SDIM) / 4; i += 512) {
            zs[i] = z4;
            zc[i] = z4;
        }
    }
    __syncthreads();   // zero-fill by whole block visible before scatter

    // ---------------- scatter ------------------------------------------------
    float vs[3] = {v0, v1, v2};
    int   is[3] = {i0, i1, i2};

    if (tid < 256) {
        // Column t's top-3 along R
        const int t = tid;
        const bool ms = srcm[(size_t)p * SDIM + t] != 0;
        #pragma unroll
        for (int k = 0; k < 3; ++k) {
            int r = is[k];
            float v = vs[k];
            atomicAdd(&oscore[r * SDIM + t], 0.5f * v);
            if (v > 0.0f && ms && refm[(size_t)p * RDIM + r] != 0)
                ocorr[r * SDIM + t] = 1.0f;   // idempotent write, benign race
        }
    } else {
        // Row t's top-3 along S
        const int t = tid - 256;
        const bool mr = refm[(size_t)p * RDIM + t] != 0;
        #pragma unroll
        for (int k = 0; k < 3; ++k) {
            int s = is[k];
            float v = vs[k];
            atomicAdd(&oscore[t * SDIM + s], 0.5f * v);
            if (v > 0.0f && mr && srcm[(size_t)p * SDIM + s] != 0)
                ocorr[t * SDIM + s] = 1.0f;
        }
    }
}

extern "C" void kernel_launch(void* const* d_in, const int* in_sizes, int n_in,
                              void* d_out, int out_size)
{
    // metadata order: matching_score_map [P,R,S] f32, node_corr_scores [P] f32 (unused),
    //                 ref_knn_masks [P,R] bool->int32, src_knn_masks [P,S] bool->int32
    const float* msm  = (const float*)d_in[0];
    const int*   refm = (const int*)d_in[2];
    const int*   srcm = (const int*)d_in[3];

    const int P = in_sizes[1];                 // node_corr_scores has P elements
    float* out_score = (float*)d_out;
    float* out_corr  = out_score + (size_t)P * RDIM * SDIM;  // bool output as float32

    ipm_kernel<<<P, 512>>>(msm, refm, srcm, out_score, out_corr);
}

// round 6
// speedup vs baseline: 1.3900x; 1.0026x over previous
#include <cuda_runtime.h>
#include <cuda_bf16.h>

#define RDIM 256
#define SDIM 256

__global__ __launch_bounds__(512)
void ipm_kernel(const float* __restrict__ msm,
                const int* __restrict__ refm,     // bool promoted to int32
                const int* __restrict__ srcm,     // bool promoted to int32
                float* __restrict__ out_score,
                float* __restrict__ out_corr)     // bool output stored as float32
{
    const int p = blockIdx.x;
    const int tid = threadIdx.x;                  // 0..511

    const float* __restrict__ tile = msm + (size_t)p * RDIM * SDIM;
    float* __restrict__ oscore = out_score + (size_t)p * RDIM * SDIM;
    float* __restrict__ ocorr  = out_corr  + (size_t)p * RDIM * SDIM;

    // top-3 of RAW scores (exp is monotonic -> same argmax set; exp applied at scatter)
    float b0 = -1e30f, b1 = -1e30f, b2 = -1e30f;
    int   j0 = 0,      j1 = 0,      j2 = 0;

    if (tid < 256) {
        // ---- column top-3 for column t = tid (scan r; coalesced across lanes)
        const int t = tid;
        #pragma unroll 8
        for (int r = 0; r < RDIM; ++r) {
            float v = tile[r * SDIM + t];
            if (v > b2) {                          // rare (~17/256 taken)
                if (v > b0)      { b2 = b1; j2 = j1; b1 = b0; j1 = j0; b0 = v; j0 = r; }
                else if (v > b1) { b2 = b1; j2 = j1; b1 = v;  j1 = r; }
                else             { b2 = v;  j2 = r; }
            }
        }
    } else {
        // ---- row top-3 for row t = tid-256 (contiguous float4 per thread)
        const int t = tid - 256;
        const float4* __restrict__ row = (const float4*)(tile + (size_t)t * SDIM);
        #pragma unroll 8
        for (int j = 0; j < SDIM / 4; ++j) {
            float4 q = row[j];
            float vals[4] = {q.x, q.y, q.z, q.w};
            #pragma unroll
            for (int u = 0; u < 4; ++u) {
                float v = vals[u];
                int s = j * 4 + u;
                if (v > b2) {
                    if (v > b0)      { b2 = b1; j2 = j1; b1 = b0; j1 = j0; b0 = v; j0 = s; }
                    else if (v > b1) { b2 = b1; j2 = j1; b1 = v;  j1 = s; }
                    else             { b2 = v;  j2 = s; }
                }
            }
        }
    }

    // ---------------- zero-fill both output tiles (512 threads, float4) ------
    {
        float4 z4 = make_float4(0.f, 0.f, 0.f, 0.f);
        float4* zs = (float4*)oscore;
        float4* zc = (float4*)ocorr;
        #pragma unroll 8
        for (int i = tid; i < (RDIM * SDIM) / 4; i += 512) {
            zs[i] = z4;
            zc[i] = z4;
        }
    }
    __syncthreads();   // zero-fill by whole block visible before scatter

    // ---------------- scatter (exp applied to the 3 winners only) ------------
    float vs[3] = {__expf(b0), __expf(b1), __expf(b2)};
    int   is[3] = {j0, j1, j2};

    if (tid < 256) {
        // Column t's top-3 along R
        const int t = tid;
        const bool ms = srcm[(size_t)p * SDIM + t] != 0;
        #pragma unroll
        for (int k = 0; k < 3; ++k) {
            int r = is[k];
            float v = vs[k];
            atomicAdd(&oscore[r * SDIM + t], 0.5f * v);
            if (v > 0.0f && ms && refm[(size_t)p * RDIM + r] != 0)
                ocorr[r * SDIM + t] = 1.0f;   // idempotent write, benign race
        }
    } else {
        // Row t's top-3 along S
        const int t = tid - 256;
        const bool mr = refm[(size_t)p * RDIM + t] != 0;
        #pragma unroll
        for (int k = 0; k < 3; ++k) {
            int s = is[k];
            float v = vs[k];
            atomicAdd(&oscore[t * SDIM + s], 0.5f * v);
            if (v > 0.0f && mr && srcm[(size_t)p * SDIM + s] != 0)
                ocorr[t * SDIM + s] = 1.0f;
        }
    }
}

extern "C" void kernel_launch(void* const* d_in, const int* in_sizes, int n_in,
                              void* d_out, int out_size)
{
    // metadata order: matching_score_map [P,R,S] f32, node_corr_scores [P] f32 (unused),
    //                 ref_knn_masks [P,R] bool->int32, src_knn_masks [P,S] bool->int32
    const float* msm  = (const float*)d_in[0];
    const int*   refm = (const int*)d_in[2];
    const int*   srcm = (const int*)d_in[3];

    const int P = in_sizes[1];                 // node_corr_scores has P elements
    float* out_score = (float*)d_out;
    float* out_corr  = out_score + (size_t)P * RDIM * SDIM;  // bool output as float32

    ipm_kernel<<<P, 512>>>(msm, refm, srcm, out_score, out_corr);
}